// round 11
// baseline (speedup 1.0000x reference)
#include <cuda_runtime.h>
#include <cuda_fp16.h>
#include <cstdint>

#define B 512
#define HID 128
#define IN_DIM 595

#define TSTR 272            // tile row stride (bytes) -> conflict-free ldmatrix
#define TILE_BYTES 34816    // 128 rows * 272

// ---------------- device scratch (no allocations allowed) ----------------
__device__ float g_scratch[4 * B * HID];               // H1, H2, U, V
__device__ __align__(16) unsigned char g_bsw[34816];   // C^T staged fp16

// ======================= helpers =======================
__device__ __forceinline__ uint32_t smem_u32(const void* p) {
    uint32_t a;
    asm("{ .reg .u64 t; cvta.to.shared.u64 t, %1; cvt.u32.u64 %0, t; }" : "=r"(a) : "l"(p));
    return a;
}
__device__ __forceinline__ void ldm4(uint32_t* r, uint32_t addr) {
    asm volatile("ldmatrix.sync.aligned.m8n8.x4.shared.b16 {%0,%1,%2,%3}, [%4];"
                 : "=r"(r[0]), "=r"(r[1]), "=r"(r[2]), "=r"(r[3]) : "r"(addr));
}
__device__ __forceinline__ void mma_fp16(float* c, const uint32_t* a, uint32_t b0, uint32_t b1) {
    asm volatile(
        "mma.sync.aligned.m16n8k16.row.col.f32.f16.f16.f32 "
        "{%0,%1,%2,%3}, {%4,%5,%6,%7}, {%8,%9}, {%0,%1,%2,%3};"
        : "+f"(c[0]), "+f"(c[1]), "+f"(c[2]), "+f"(c[3])
        : "r"(a[0]), "r"(a[1]), "r"(a[2]), "r"(a[3]), "r"(b0), "r"(b1));
}

// ======================= encoder GEMM (K=595, 3 rows/block, grid 171) =======================
__global__ __launch_bounds__(512) void enc_gemm(const float* __restrict__ X,
                                                const float* __restrict__ W,
                                                const float* __restrict__ bias,
                                                float* __restrict__ Y, int K, int doRelu) {
    __shared__ float Xs[3 * 608];
    __shared__ float red[3][3][128];
    const int tid = threadIdx.x;
    const int n = tid & 127, q = tid >> 7;
    const int m0 = blockIdx.x * 3;
    const int nrows = (m0 + 3 <= B) ? 3 : (B - m0);
    for (int idx = tid; idx < nrows * K; idx += 512) {
        int r = idx / K, k = idx - r * K;
        Xs[r * 608 + k] = X[(size_t)(m0 + r) * K + k];
    }
    __syncthreads();
    const int kb = (K * q) >> 2, ke = (K * (q + 1)) >> 2;
    float a0 = 0.f, a1 = 0.f, a2 = 0.f;
    const float* Wn = W + n;
#pragma unroll 8
    for (int k = kb; k < ke; ++k) {
        float w = __ldg(Wn + k * 128);
        a0 = fmaf(Xs[k], w, a0);
        a1 = fmaf(Xs[608 + k], w, a1);
        a2 = fmaf(Xs[1216 + k], w, a2);
    }
    if (q) {
        red[q - 1][0][n] = a0; red[q - 1][1][n] = a1; red[q - 1][2][n] = a2;
    }
    __syncthreads();
    if (q == 0) {
        float bv = bias ? bias[n] : 0.f;
        float r0 = a0 + red[0][0][n] + red[1][0][n] + red[2][0][n] + bv;
        float r1 = a1 + red[0][1][n] + red[1][1][n] + red[2][1][n] + bv;
        float r2 = a2 + red[0][2][n] + red[1][2][n] + red[2][2][n] + bv;
        if (doRelu) { r0 = fmaxf(r0, 0.f); r1 = fmaxf(r1, 0.f); r2 = fmaxf(r2, 0.f); }
        Y[(size_t)(m0 + 0) * 128 + n] = r0;
        if (nrows > 1) Y[(size_t)(m0 + 1) * 128 + n] = r1;
        if (nrows > 2) Y[(size_t)(m0 + 2) * 128 + n] = r2;
    }
}

// ======================= fused rest-of-encoder + prep (2 rows/block) =======================
// blocks [0,256): rows 2m,2m+1 — h2 = relu(H1@W2 + b2); U = h2@A + bp1; V = h2@Bm.
// blocks [256,288): stage C^T fp16 into g_bsw (16384 elems, 512/block).
__global__ __launch_bounds__(512) void enc_rest(const float* __restrict__ H1,
                                                const float* __restrict__ W2,
                                                const float* __restrict__ b2,
                                                const float* __restrict__ Wp1,
                                                const float* __restrict__ bp1,
                                                float* __restrict__ H2,
                                                float* __restrict__ U, float* __restrict__ V) {
    const int tid = threadIdx.x;
    const int bx = blockIdx.x;
    if (bx >= 256) {
        int idx = (bx - 256) * 512 + tid;           // < 16384
        int k = idx >> 7, d = idx & 127;
        float v = Wp1[(256 + d) * 128 + k];
        *(__half*)(g_bsw + (uint32_t)k * TSTR + d * 2) = __float2half_rn(v);
        return;
    }
    __shared__ float h1s[256], h2s[256];
    __shared__ float red[3][2][128];
    __shared__ float red2[2][256];
    const int m0 = bx * 2;
    const int n = tid & 127, q = tid >> 7;          // 4-way K split
    if (tid < 256) h1s[tid] = H1[(size_t)m0 * 128 + tid];
    __syncthreads();

    // stage 1: h2 for both rows
    {
        float a0 = 0.f, a1 = 0.f;
        const float* Wn = W2 + n;
#pragma unroll 8
        for (int k = q * 32; k < q * 32 + 32; ++k) {
            float w = __ldg(Wn + k * 128);
            a0 = fmaf(h1s[k], w, a0);
            a1 = fmaf(h1s[128 + k], w, a1);
        }
        if (q) { red[q - 1][0][n] = a0; red[q - 1][1][n] = a1; }
        __syncthreads();
        if (q == 0) {
            float bv = b2[n];
            float r0 = fmaxf(a0 + red[0][0][n] + red[1][0][n] + red[2][0][n] + bv, 0.f);
            float r1 = fmaxf(a1 + red[0][1][n] + red[1][1][n] + red[2][1][n] + bv, 0.f);
            h2s[n] = r0; h2s[128 + n] = r1;
            H2[(size_t)m0 * 128 + n] = r0;
            H2[(size_t)(m0 + 1) * 128 + n] = r1;
        }
        __syncthreads();
    }

    // stage 2: U and V for both rows (256 cols, 2-way K split)
    {
        const int col = tid & 255, q2 = tid >> 8;
        const float* Wc = (col < 128) ? (Wp1 + col) : (Wp1 + 128 * 128 + (col - 128));
        float a0 = 0.f, a1 = 0.f;
#pragma unroll 8
        for (int k = q2 * 64; k < q2 * 64 + 64; ++k) {
            float w = __ldg(Wc + k * 128);
            a0 = fmaf(h2s[k], w, a0);
            a1 = fmaf(h2s[128 + k], w, a1);
        }
        if (q2) { red2[0][col] = a0; red2[1][col] = a1; }
        __syncthreads();
        if (q2 == 0) {
            float bv = (col < 128) ? bp1[col] : 0.f;
            float r0 = a0 + red2[0][col] + bv;
            float r1 = a1 + red2[1][col] + bv;
            float* dst = (col < 128) ? U : V;
            int c = col & 127;
            dst[(size_t)m0 * 128 + c] = r0;
            dst[(size_t)(m0 + 1) * 128 + c] = r1;
        }
    }
}

// ======================= pairwise kernel: 8 i per CTA, occ 2, 2 syncs/ii ===========
#define OFF_A   0
#define OFF_B   34816
#define OFF_HJ  69632
#define OFF_HIS 104448       // 8 * 256 B fp16
#define OFF_US  106496       // 8 * 512 B fp32
#define OFF_W2  110592
#define OFF_RED 111104
#define SMEM_PAIR 113152

__global__ __launch_bounds__(256, 2) void pair_mma(
    const float* __restrict__ H, const float* __restrict__ U, const float* __restrict__ V,
    const float* __restrict__ Wp2, const float* __restrict__ bp2, float* __restrict__ out) {
    extern __shared__ char sm[];
    const uint32_t sb = smem_u32(sm);
    float* w2  = (float*)(sm + OFF_W2);
    float* red = (float*)(sm + OFF_RED);

    const int tid  = threadIdx.x;
    const int lane = tid & 31, wid = tid >> 5;
    const int wm = wid & 1, wn = wid >> 1;     // warp tile: 64 j-rows x 32 k-cols
    const int i_base = blockIdx.x * 8;
    const int j0 = blockIdx.y * 128;

    // ---- stage B (C^T fp16, 34816 B = 2176 uint4) ----
    {
        const uint4* g = (const uint4*)g_bsw;
        uint4* s = (uint4*)(sm + OFF_B);
#pragma unroll
        for (int t = 0; t < 9; ++t) {
            int idx = tid + t * 256;
            if (idx < 2176) s[idx] = g[idx];
        }
    }
    const int j  = tid >> 1;
    const int dh = (tid & 1) << 6;

    // ---- stage HJ: fp16(h_j) tile ----
    {
        const float4* Hj = (const float4*)(H + (size_t)(j0 + j) * HID + dh);
        char* row = sm + OFF_HJ + (uint32_t)j * TSTR + dh * 2;
#pragma unroll
        for (int t = 0; t < 8; ++t) {
            float4 v0 = Hj[2 * t], v1 = Hj[2 * t + 1];
            __half2 a0 = __floats2half2_rn(v0.x, v0.y);
            __half2 a1 = __floats2half2_rn(v0.z, v0.w);
            __half2 a2 = __floats2half2_rn(v1.x, v1.y);
            __half2 a3 = __floats2half2_rn(v1.z, v1.w);
            uint4 o;
            o.x = *(uint32_t*)&a0; o.y = *(uint32_t*)&a1;
            o.z = *(uint32_t*)&a2; o.w = *(uint32_t*)&a3;
            *(uint4*)(row + t * 16) = o;
        }
    }
    // ---- stage his (fp16) and Us (fp32); w2 ----
    if (tid < 128) {
#pragma unroll
        for (int ii = 0; ii < 8; ++ii) {
            float hv = H[(size_t)(i_base + ii) * HID + tid];
            *(__half*)(sm + OFF_HIS + ii * 256 + tid * 2) = __float2half_rn(hv);
            *(float*)(sm + OFF_US + ii * 512 + tid * 4) = U[(size_t)(i_base + ii) * HID + tid];
        }
        w2[tid] = Wp2[tid];
    }

    const uint32_t aAddrBase = sb + OFF_A + (uint32_t)(wm * 64 + (lane & 15)) * TSTR + (lane >> 4) * 16;
    const uint32_t bAddrBase = sb + OFF_B + (uint32_t)(wn * 32 + (lane & 15)) * TSTR + (lane >> 4) * 16;
    const char* hjRow = sm + OFF_HJ + (uint32_t)j * TSTR + dh * 2;
    char* aRow = sm + OFF_A + (uint32_t)j * TSTR + dh * 2;
    const float b2v = bp2[0];
    const int kb = wn * 32;

    __syncthreads();

    for (int ii = 0; ii < 8; ++ii) {
        // ---- out-write of previous ii (reads red) overlapped with A-build ----
        if (ii > 0 && tid < 128) {
            float s = red[tid] + red[128 + tid] + red[256 + tid] + red[384 + tid] + b2v;
            out[(size_t)(i_base + ii - 1) * B + j0 + tid] = s;
        }
        // ---- build A: A[j][d] = |hj - hi| fp16 ----
        {
            const __half2* hi2 = (const __half2*)(sm + OFF_HIS + ii * 256 + dh * 2);
#pragma unroll
            for (int m = 0; m < 8; ++m) {
                uint4 hv = *(const uint4*)(hjRow + m * 16);
                __half2 j0h = *(__half2*)&hv.x, j1h = *(__half2*)&hv.y;
                __half2 j2h = *(__half2*)&hv.z, j3h = *(__half2*)&hv.w;
                __half2 t0 = __habs2(__hsub2(j0h, hi2[4 * m + 0]));
                __half2 t1 = __habs2(__hsub2(j1h, hi2[4 * m + 1]));
                __half2 t2 = __habs2(__hsub2(j2h, hi2[4 * m + 2]));
                __half2 t3 = __habs2(__hsub2(j3h, hi2[4 * m + 3]));
                uint4 o;
                o.x = *(uint32_t*)&t0; o.y = *(uint32_t*)&t1;
                o.z = *(uint32_t*)&t2; o.w = *(uint32_t*)&t3;
                *(uint4*)(aRow + m * 16) = o;
            }
        }
        __syncthreads();   // A ready; prev out-write done

        // ---- MMA: single-term fp16 ----
        float acc[4][4][4];
#pragma unroll
        for (int a = 0; a < 4; ++a)
#pragma unroll
            for (int b = 0; b < 4; ++b) {
                acc[a][b][0] = 0.f; acc[a][b][1] = 0.f;
                acc[a][b][2] = 0.f; acc[a][b][3] = 0.f;
            }
#pragma unroll
        for (int ks = 0; ks < 8; ++ks) {
            uint32_t af[4][4], bh[2][4];
#pragma unroll
            for (int mt = 0; mt < 4; ++mt)
                ldm4(af[mt], aAddrBase + mt * (16 * TSTR) + ks * 32);
#pragma unroll
            for (int p = 0; p < 2; ++p)
                ldm4(bh[p], bAddrBase + p * (16 * TSTR) + ks * 32);
#pragma unroll
            for (int mt = 0; mt < 4; ++mt)
#pragma unroll
                for (int nt = 0; nt < 4; ++nt)
                    mma_fp16(acc[mt][nt], af[mt],
                             bh[nt >> 1][nt & 1], bh[nt >> 1][(nt & 1) + 2]);
        }

        // ---- epilogue: relu(acc + U_i + V_j) . w2, partial k-sums to red ----
        const float* Usi = (const float*)(sm + OFF_US + ii * 512);
#pragma unroll
        for (int mt = 0; mt < 4; ++mt) {
            const int r0 = wm * 64 + mt * 16 + (lane >> 2);
            float p0 = 0.f, p1 = 0.f;
#pragma unroll
            for (int nt = 0; nt < 4; ++nt) {
                const int k = kb + nt * 8 + (lane & 3) * 2;
                float2 v0 = __ldg((const float2*)(V + (size_t)(j0 + r0) * HID + k));
                float2 v1 = __ldg((const float2*)(V + (size_t)(j0 + r0 + 8) * HID + k));
                float u0 = Usi[k], u1 = Usi[k + 1];
                float w0 = w2[k], w1 = w2[k + 1];
                p0 = fmaf(fmaxf(acc[mt][nt][0] + u0 + v0.x, 0.f), w0, p0);
                p0 = fmaf(fmaxf(acc[mt][nt][1] + u1 + v0.y, 0.f), w1, p0);
                p1 = fmaf(fmaxf(acc[mt][nt][2] + u0 + v1.x, 0.f), w0, p1);
                p1 = fmaf(fmaxf(acc[mt][nt][3] + u1 + v1.y, 0.f), w1, p1);
            }
            p0 += __shfl_down_sync(0xffffffffu, p0, 2, 4);
            p0 += __shfl_down_sync(0xffffffffu, p0, 1, 4);
            p1 += __shfl_down_sync(0xffffffffu, p1, 2, 4);
            p1 += __shfl_down_sync(0xffffffffu, p1, 1, 4);
            if ((lane & 3) == 0) {
                red[wn * 128 + r0]     = p0;
                red[wn * 128 + r0 + 8] = p1;
            }
        }
        __syncthreads();   // red complete (and A free for next build)
    }
    // final out-write
    if (tid < 128) {
        float s = red[tid] + red[128 + tid] + red[256 + tid] + red[384 + tid] + b2v;
        out[(size_t)(i_base + 7) * B + j0 + tid] = s;
    }
}

// ======================= launch =======================
extern "C" void kernel_launch(void* const* d_in, const int* in_sizes, int n_in,
                              void* d_out, int out_size) {
    const float* x   = (const float*)d_in[0];
    const float* W1  = (const float*)d_in[1];
    const float* b1  = (const float*)d_in[2];
    const float* W2  = (const float*)d_in[3];
    const float* b2  = (const float*)d_in[4];
    const float* Wp1 = (const float*)d_in[5];
    const float* bp1 = (const float*)d_in[6];
    const float* Wp2 = (const float*)d_in[7];
    const float* bp2 = (const float*)d_in[8];
    float* out = (float*)d_out;

    float* sp = nullptr;
    cudaGetSymbolAddress((void**)&sp, g_scratch);
    float* H1 = sp;
    float* H2 = sp + B * HID;
    float* U  = sp + 2 * B * HID;
    float* V  = sp + 3 * B * HID;

    enc_gemm<<<(B + 2) / 3, 512>>>(x, W1, b1, H1, IN_DIM, 1);
    enc_rest<<<B / 2 + 32, 512>>>(H1, W2, b2, Wp1, bp1, H2, U, V);

    cudaFuncSetAttribute(pair_mma, cudaFuncAttributeMaxDynamicSharedMemorySize, SMEM_PAIR);
    dim3 grid(B / 8, B / 128);
    pair_mma<<<grid, 256, SMEM_PAIR>>>(H2, U, V, Wp2, bp2, out);
}

// round 12
// speedup vs baseline: 1.1933x; 1.1933x over previous
#include <cuda_runtime.h>
#include <cuda_fp16.h>
#include <cstdint>

#define B 512
#define HID 128
#define IN_DIM 595

#define TSTR 272            // tile row stride (bytes) -> conflict-free ldmatrix
#define TILE_BYTES 34816    // 128 rows * 272

// ---------------- device scratch (no allocations allowed) ----------------
__device__ float g_scratch[4 * B * HID];               // H1, H2, U, V
__device__ __align__(16) unsigned char g_bsw[34816];   // C^T staged fp16

// ======================= helpers =======================
__device__ __forceinline__ uint32_t smem_u32(const void* p) {
    uint32_t a;
    asm("{ .reg .u64 t; cvta.to.shared.u64 t, %1; cvt.u32.u64 %0, t; }" : "=r"(a) : "l"(p));
    return a;
}
__device__ __forceinline__ void ldm4(uint32_t* r, uint32_t addr) {
    asm volatile("ldmatrix.sync.aligned.m8n8.x4.shared.b16 {%0,%1,%2,%3}, [%4];"
                 : "=r"(r[0]), "=r"(r[1]), "=r"(r[2]), "=r"(r[3]) : "r"(addr));
}
__device__ __forceinline__ void mma_fp16(float* c, const uint32_t* a, uint32_t b0, uint32_t b1) {
    asm volatile(
        "mma.sync.aligned.m16n8k16.row.col.f32.f16.f16.f32 "
        "{%0,%1,%2,%3}, {%4,%5,%6,%7}, {%8,%9}, {%0,%1,%2,%3};"
        : "+f"(c[0]), "+f"(c[1]), "+f"(c[2]), "+f"(c[3])
        : "r"(a[0]), "r"(a[1]), "r"(a[2]), "r"(a[3]), "r"(b0), "r"(b1));
}

// ======================= encoder GEMM (K=595, 2 rows/block, grid 256) =============
__global__ __launch_bounds__(512) void enc_gemm(const float* __restrict__ X,
                                                const float* __restrict__ W,
                                                const float* __restrict__ bias,
                                                float* __restrict__ Y, int K, int doRelu) {
    __shared__ float Xs[2 * 608];
    __shared__ float red[3][2][128];
    const int tid = threadIdx.x;
    const int n = tid & 127, q = tid >> 7;
    const int m0 = blockIdx.x * 2;
    for (int idx = tid; idx < 2 * K; idx += 512) {
        int r = idx < K ? 0 : 1, k = idx < K ? idx : idx - K;
        Xs[r * 608 + k] = X[(size_t)(m0 + r) * K + k];
    }
    __syncthreads();
    const int kb = (K * q) >> 2, ke = (K * (q + 1)) >> 2;
    float a0 = 0.f, a1 = 0.f;
    const float* Wn = W + n;
#pragma unroll 8
    for (int k = kb; k < ke; ++k) {
        float w = __ldg(Wn + k * 128);
        a0 = fmaf(Xs[k], w, a0);
        a1 = fmaf(Xs[608 + k], w, a1);
    }
    if (q) { red[q - 1][0][n] = a0; red[q - 1][1][n] = a1; }
    __syncthreads();
    if (q == 0) {
        float bv = bias ? bias[n] : 0.f;
        float r0 = a0 + red[0][0][n] + red[1][0][n] + red[2][0][n] + bv;
        float r1 = a1 + red[0][1][n] + red[1][1][n] + red[2][1][n] + bv;
        if (doRelu) { r0 = fmaxf(r0, 0.f); r1 = fmaxf(r1, 0.f); }
        Y[(size_t)(m0 + 0) * 128 + n] = r0;
        Y[(size_t)(m0 + 1) * 128 + n] = r1;
    }
}

// ======================= fused rest-of-encoder + prep (1 row/block, grid 512+32) ====
__global__ __launch_bounds__(512) void enc_rest(const float* __restrict__ H1,
                                                const float* __restrict__ W2,
                                                const float* __restrict__ b2,
                                                const float* __restrict__ Wp1,
                                                const float* __restrict__ bp1,
                                                float* __restrict__ H2,
                                                float* __restrict__ U, float* __restrict__ V) {
    const int tid = threadIdx.x;
    const int bx = blockIdx.x;
    if (bx >= 512) {
        int idx = (bx - 512) * 512 + tid;           // < 16384
        int k = idx >> 7, d = idx & 127;
        float v = Wp1[(256 + d) * 128 + k];
        *(__half*)(g_bsw + (uint32_t)k * TSTR + d * 2) = __float2half_rn(v);
        return;
    }
    __shared__ float h1s[128], h2s[128];
    __shared__ float red[3][128];
    __shared__ float red2[256];
    const int m = bx;
    const int n = tid & 127, q = tid >> 7;          // 4-way K split
    if (tid < 128) h1s[tid] = H1[(size_t)m * 128 + tid];
    __syncthreads();
    {
        float a = 0.f;
        const float* Wn = W2 + n;
#pragma unroll 8
        for (int k = q * 32; k < q * 32 + 32; ++k)
            a = fmaf(h1s[k], __ldg(Wn + k * 128), a);
        if (q) red[q - 1][n] = a;
        __syncthreads();
        if (q == 0) {
            float r = fmaxf(a + red[0][n] + red[1][n] + red[2][n] + b2[n], 0.f);
            h2s[n] = r;
            H2[(size_t)m * 128 + n] = r;
        }
        __syncthreads();
    }
    {
        const int col = tid & 255, q2 = tid >> 8;
        const float* Wc = (col < 128) ? (Wp1 + col) : (Wp1 + 128 * 128 + (col - 128));
        float a = 0.f;
#pragma unroll 8
        for (int k = q2 * 64; k < q2 * 64 + 64; ++k)
            a = fmaf(h2s[k], __ldg(Wc + k * 128), a);
        if (q2) red2[col] = a;
        __syncthreads();
        if (q2 == 0) {
            float r = a + red2[col] + (col < 128 ? bp1[col] : 0.f);
            float* dst = (col < 128) ? U : V;
            dst[(size_t)m * 128 + (col & 127)] = r;
        }
    }
}

// ======================= pairwise kernel: 8 i per CTA, occ 2, warp-owns-full-k ======
// grid (64, 4). Warp w owns j rows [w*16, w*16+16), all 128 k. No cross-warp
// reduction: quad shfl + direct STG per ii. 2 syncs per ii.
#define OFF_A   0
#define OFF_B   34816
#define OFF_HJ  69632
#define OFF_HIS 104448       // 8 * 256 B fp16
#define OFF_US  106496       // 8 * 512 B fp32
#define OFF_W2  110592
#define SMEM_PAIR 111104

__global__ __launch_bounds__(256, 2) void pair_mma(
    const float* __restrict__ H, const float* __restrict__ U, const float* __restrict__ V,
    const float* __restrict__ Wp2, const float* __restrict__ bp2, float* __restrict__ out) {
    extern __shared__ char sm[];
    const uint32_t sb = smem_u32(sm);
    float* w2 = (float*)(sm + OFF_W2);

    const int tid  = threadIdx.x;
    const int lane = tid & 31, wid = tid >> 5;
    const int i_base = blockIdx.x * 8;
    const int j0 = blockIdx.y * 128;

    // ---- stage B (C^T fp16, 34816 B = 2176 uint4) ----
    {
        const uint4* g = (const uint4*)g_bsw;
        uint4* s = (uint4*)(sm + OFF_B);
#pragma unroll
        for (int t = 0; t < 9; ++t) {
            int idx = tid + t * 256;
            if (idx < 2176) s[idx] = g[idx];
        }
    }
    const int j  = tid >> 1;
    const int dh = (tid & 1) << 6;

    // ---- stage HJ: fp16(h_j) tile ----
    {
        const float4* Hj = (const float4*)(H + (size_t)(j0 + j) * HID + dh);
        char* row = sm + OFF_HJ + (uint32_t)j * TSTR + dh * 2;
#pragma unroll
        for (int t = 0; t < 8; ++t) {
            float4 v0 = Hj[2 * t], v1 = Hj[2 * t + 1];
            __half2 a0 = __floats2half2_rn(v0.x, v0.y);
            __half2 a1 = __floats2half2_rn(v0.z, v0.w);
            __half2 a2 = __floats2half2_rn(v1.x, v1.y);
            __half2 a3 = __floats2half2_rn(v1.z, v1.w);
            uint4 o;
            o.x = *(uint32_t*)&a0; o.y = *(uint32_t*)&a1;
            o.z = *(uint32_t*)&a2; o.w = *(uint32_t*)&a3;
            *(uint4*)(row + t * 16) = o;
        }
    }
    // ---- stage his (fp16) and Us (fp32); w2 ----
    if (tid < 128) {
#pragma unroll
        for (int ii = 0; ii < 8; ++ii) {
            float hv = H[(size_t)(i_base + ii) * HID + tid];
            *(__half*)(sm + OFF_HIS + ii * 256 + tid * 2) = __float2half_rn(hv);
            *(float*)(sm + OFF_US + ii * 512 + tid * 4) = U[(size_t)(i_base + ii) * HID + tid];
        }
        w2[tid] = Wp2[tid];
    }
    __syncthreads();

    const uint32_t aAddrBase = sb + OFF_A + (uint32_t)(wid * 16 + (lane & 15)) * TSTR + (lane >> 4) * 16;
    const uint32_t bAddrBase = sb + OFF_B + (uint32_t)(lane & 15) * TSTR + (lane >> 4) * 16;
    const char* hjRow = sm + OFF_HJ + (uint32_t)j * TSTR + dh * 2;
    char* aRow = sm + OFF_A + (uint32_t)j * TSTR + dh * 2;
    const float b2v = bp2[0];
    const int jl0 = wid * 16 + (lane >> 2);    // this thread's first j row (local)
    const int kq  = (lane & 3) * 2;            // k offset within 8-col tile

    for (int ii = 0; ii < 8; ++ii) {
        // ---- build A: A[j][d] = |hj - hi| fp16 ----
        {
            const __half2* hi2 = (const __half2*)(sm + OFF_HIS + ii * 256 + dh * 2);
#pragma unroll
            for (int m = 0; m < 8; ++m) {
                uint4 hv = *(const uint4*)(hjRow + m * 16);
                __half2 j0h = *(__half2*)&hv.x, j1h = *(__half2*)&hv.y;
                __half2 j2h = *(__half2*)&hv.z, j3h = *(__half2*)&hv.w;
                __half2 t0 = __habs2(__hsub2(j0h, hi2[4 * m + 0]));
                __half2 t1 = __habs2(__hsub2(j1h, hi2[4 * m + 1]));
                __half2 t2 = __habs2(__hsub2(j2h, hi2[4 * m + 2]));
                __half2 t3 = __habs2(__hsub2(j3h, hi2[4 * m + 3]));
                uint4 o;
                o.x = *(uint32_t*)&t0; o.y = *(uint32_t*)&t1;
                o.z = *(uint32_t*)&t2; o.w = *(uint32_t*)&t3;
                *(uint4*)(aRow + m * 16) = o;
            }
        }
        __syncthreads();   // A ready

        // ---- MMA: 1 A-fragment x 16 n-tiles per ks, B in two halves ----
        float acc[16][4];
#pragma unroll
        for (int nt = 0; nt < 16; ++nt) {
            acc[nt][0] = 0.f; acc[nt][1] = 0.f; acc[nt][2] = 0.f; acc[nt][3] = 0.f;
        }
#pragma unroll
        for (int ks = 0; ks < 8; ++ks) {
            uint32_t af[4];
            ldm4(af, aAddrBase + ks * 32);
            {
                uint32_t bh[4][4];
#pragma unroll
                for (int p = 0; p < 4; ++p)
                    ldm4(bh[p], bAddrBase + p * (16 * TSTR) + ks * 32);
#pragma unroll
                for (int nt = 0; nt < 8; ++nt)
                    mma_fp16(acc[nt], af, bh[nt >> 1][nt & 1], bh[nt >> 1][(nt & 1) + 2]);
            }
            {
                uint32_t bh[4][4];
#pragma unroll
                for (int p = 0; p < 4; ++p)
                    ldm4(bh[p], bAddrBase + (p + 4) * (16 * TSTR) + ks * 32);
#pragma unroll
                for (int nt = 8; nt < 16; ++nt)
                    mma_fp16(acc[nt], af, bh[(nt - 8) >> 1][nt & 1], bh[(nt - 8) >> 1][(nt & 1) + 2]);
            }
        }

        // ---- epilogue: warp-local relu-dot over full k, quad reduce, direct STG ----
        const float* Usi = (const float*)(sm + OFF_US + ii * 512);
        float p0 = 0.f, p1 = 0.f;
#pragma unroll
        for (int nt = 0; nt < 16; ++nt) {
            const int k = nt * 8 + kq;
            float2 v0 = __ldg((const float2*)(V + (size_t)(j0 + jl0) * HID + k));
            float2 v1 = __ldg((const float2*)(V + (size_t)(j0 + jl0 + 8) * HID + k));
            float u0 = Usi[k], u1 = Usi[k + 1];
            float w0 = w2[k], w1 = w2[k + 1];
            p0 = fmaf(fmaxf(acc[nt][0] + u0 + v0.x, 0.f), w0, p0);
            p0 = fmaf(fmaxf(acc[nt][1] + u1 + v0.y, 0.f), w1, p0);
            p1 = fmaf(fmaxf(acc[nt][2] + u0 + v1.x, 0.f), w0, p1);
            p1 = fmaf(fmaxf(acc[nt][3] + u1 + v1.y, 0.f), w1, p1);
        }
        p0 += __shfl_down_sync(0xffffffffu, p0, 2, 4);
        p0 += __shfl_down_sync(0xffffffffu, p0, 1, 4);
        p1 += __shfl_down_sync(0xffffffffu, p1, 2, 4);
        p1 += __shfl_down_sync(0xffffffffu, p1, 1, 4);
        if ((lane & 3) == 0) {
            out[(size_t)(i_base + ii) * B + j0 + jl0]     = p0 + b2v;
            out[(size_t)(i_base + ii) * B + j0 + jl0 + 8] = p1 + b2v;
        }
        __syncthreads();   // A free for next build
    }
}

// ======================= launch =======================
extern "C" void kernel_launch(void* const* d_in, const int* in_sizes, int n_in,
                              void* d_out, int out_size) {
    const float* x   = (const float*)d_in[0];
    const float* W1  = (const float*)d_in[1];
    const float* b1  = (const float*)d_in[2];
    const float* W2  = (const float*)d_in[3];
    const float* b2  = (const float*)d_in[4];
    const float* Wp1 = (const float*)d_in[5];
    const float* bp1 = (const float*)d_in[6];
    const float* Wp2 = (const float*)d_in[7];
    const float* bp2 = (const float*)d_in[8];
    float* out = (float*)d_out;

    float* sp = nullptr;
    cudaGetSymbolAddress((void**)&sp, g_scratch);
    float* H1 = sp;
    float* H2 = sp + B * HID;
    float* U  = sp + 2 * B * HID;
    float* V  = sp + 3 * B * HID;

    enc_gemm<<<B / 2, 512>>>(x, W1, b1, H1, IN_DIM, 1);
    enc_rest<<<B + 32, 512>>>(H1, W2, b2, Wp1, bp1, H2, U, V);

    cudaFuncSetAttribute(pair_mma, cudaFuncAttributeMaxDynamicSharedMemorySize, SMEM_PAIR);
    dim3 grid(B / 8, B / 128);
    pair_mma<<<grid, 256, SMEM_PAIR>>>(H2, U, V, Wp2, bp2, out);
}

// round 13
// speedup vs baseline: 1.1942x; 1.0008x over previous
#include <cuda_runtime.h>
#include <cuda_fp16.h>
#include <cstdint>

#define B 512
#define HID 128
#define IN_DIM 595

#define TSTR 272            // tile row stride (bytes) -> conflict-free ldmatrix
#define TILE_BYTES 34816    // 128 rows * 272

// ---------------- device scratch (no allocations allowed) ----------------
__device__ float g_scratch[3 * B * HID];               // H2, U, V
__device__ __align__(16) unsigned char g_bsw[34816];   // C^T staged fp16

// ======================= helpers =======================
__device__ __forceinline__ uint32_t smem_u32(const void* p) {
    uint32_t a;
    asm("{ .reg .u64 t; cvta.to.shared.u64 t, %1; cvt.u32.u64 %0, t; }" : "=r"(a) : "l"(p));
    return a;
}
__device__ __forceinline__ void ldm4(uint32_t* r, uint32_t addr) {
    asm volatile("ldmatrix.sync.aligned.m8n8.x4.shared.b16 {%0,%1,%2,%3}, [%4];"
                 : "=r"(r[0]), "=r"(r[1]), "=r"(r[2]), "=r"(r[3]) : "r"(addr));
}
__device__ __forceinline__ void mma_fp16(float* c, const uint32_t* a, uint32_t b0, uint32_t b1) {
    asm volatile(
        "mma.sync.aligned.m16n8k16.row.col.f32.f16.f16.f32 "
        "{%0,%1,%2,%3}, {%4,%5,%6,%7}, {%8,%9}, {%0,%1,%2,%3};"
        : "+f"(c[0]), "+f"(c[1]), "+f"(c[2]), "+f"(c[3])
        : "r"(a[0]), "r"(a[1]), "r"(a[2]), "r"(a[3]), "r"(b0), "r"(b1));
}

// ======================= fused encoder (whole chain) + prep =======================
// blocks [0,256): rows 2m,2m+1:
//   h1 = relu(x@W1 + b1)      (smem only)
//   h2 = relu(h1@W2 + b2)     -> H2
//   U  = h2@Wp1[0:128]  + bp1 -> U
//   V  = h2@Wp1[128:256]      -> V
// blocks [256,288): stage C^T fp16 into g_bsw (16384 elems, 512/block).
__global__ __launch_bounds__(512) void enc_all(const float* __restrict__ x,
                                               const float* __restrict__ W1,
                                               const float* __restrict__ b1,
                                               const float* __restrict__ W2,
                                               const float* __restrict__ b2,
                                               const float* __restrict__ Wp1,
                                               const float* __restrict__ bp1,
                                               float* __restrict__ H2,
                                               float* __restrict__ U, float* __restrict__ V) {
    const int tid = threadIdx.x;
    const int bx = blockIdx.x;
    if (bx >= 256) {
        int idx = (bx - 256) * 512 + tid;           // < 16384
        int k = idx >> 7, d = idx & 127;
        float v = Wp1[(256 + d) * 128 + k];
        *(__half*)(g_bsw + (uint32_t)k * TSTR + d * 2) = __float2half_rn(v);
        return;
    }
    __shared__ float Xs[2 * 608];
    __shared__ float h1s[2][128], h2s[2][128];
    __shared__ float red[3][2][128];
    __shared__ float red2[2][256];
    const int m0 = bx * 2;
    const int n = tid & 127, q = tid >> 7;          // 4-way K split

    // ---- stage 1: h1 = relu(x@W1 + b1) for 2 rows ----
    for (int idx = tid; idx < 2 * IN_DIM; idx += 512) {
        int r = idx < IN_DIM ? 0 : 1, k = idx < IN_DIM ? idx : idx - IN_DIM;
        Xs[r * 608 + k] = x[(size_t)(m0 + r) * IN_DIM + k];
    }
    __syncthreads();
    {
        const int kb = (IN_DIM * q) >> 2, ke = (IN_DIM * (q + 1)) >> 2;
        float a0 = 0.f, a1 = 0.f;
        const float* Wn = W1 + n;
#pragma unroll 8
        for (int k = kb; k < ke; ++k) {
            float w = __ldg(Wn + k * 128);
            a0 = fmaf(Xs[k], w, a0);
            a1 = fmaf(Xs[608 + k], w, a1);
        }
        if (q) { red[q - 1][0][n] = a0; red[q - 1][1][n] = a1; }
        __syncthreads();
        if (q == 0) {
            float bv = b1[n];
            h1s[0][n] = fmaxf(a0 + red[0][0][n] + red[1][0][n] + red[2][0][n] + bv, 0.f);
            h1s[1][n] = fmaxf(a1 + red[0][1][n] + red[1][1][n] + red[2][1][n] + bv, 0.f);
        }
        __syncthreads();
    }

    // ---- stage 2: h2 = relu(h1@W2 + b2) for 2 rows ----
    {
        float a0 = 0.f, a1 = 0.f;
        const float* Wn = W2 + n;
#pragma unroll 8
        for (int k = q * 32; k < q * 32 + 32; ++k) {
            float w = __ldg(Wn + k * 128);
            a0 = fmaf(h1s[0][k], w, a0);
            a1 = fmaf(h1s[1][k], w, a1);
        }
        if (q) { red[q - 1][0][n] = a0; red[q - 1][1][n] = a1; }
        __syncthreads();
        if (q == 0) {
            float bv = b2[n];
            float r0 = fmaxf(a0 + red[0][0][n] + red[1][0][n] + red[2][0][n] + bv, 0.f);
            float r1 = fmaxf(a1 + red[0][1][n] + red[1][1][n] + red[2][1][n] + bv, 0.f);
            h2s[0][n] = r0; h2s[1][n] = r1;
            H2[(size_t)m0 * 128 + n] = r0;
            H2[(size_t)(m0 + 1) * 128 + n] = r1;
        }
        __syncthreads();
    }

    // ---- stage 3: U and V for 2 rows (256 cols, 2-way K split) ----
    {
        const int col = tid & 255, q2 = tid >> 8;
        const float* Wc = (col < 128) ? (Wp1 + col) : (Wp1 + 128 * 128 + (col - 128));
        float a0 = 0.f, a1 = 0.f;
#pragma unroll 8
        for (int k = q2 * 64; k < q2 * 64 + 64; ++k) {
            float w = __ldg(Wc + k * 128);
            a0 = fmaf(h2s[0][k], w, a0);
            a1 = fmaf(h2s[1][k], w, a1);
        }
        if (q2) { red2[0][col] = a0; red2[1][col] = a1; }
        __syncthreads();
        if (q2 == 0) {
            float bv = (col < 128) ? bp1[col] : 0.f;
            float r0 = a0 + red2[0][col] + bv;
            float r1 = a1 + red2[1][col] + bv;
            float* dst = (col < 128) ? U : V;
            int c = col & 127;
            dst[(size_t)m0 * 128 + c] = r0;
            dst[(size_t)(m0 + 1) * 128 + c] = r1;
        }
    }
}

// ======================= pairwise kernel: 8 i per CTA, occ 2, warp-owns-full-k ======
// grid (64, 4). Warp w owns j rows [w*16, w*16+16), all 128 k. No cross-warp
// reduction: quad shfl + direct STG per ii. 2 syncs per ii.  (round-12 exact)
#define OFF_A   0
#define OFF_B   34816
#define OFF_HJ  69632
#define OFF_HIS 104448       // 8 * 256 B fp16
#define OFF_US  106496       // 8 * 512 B fp32
#define OFF_W2  110592
#define SMEM_PAIR 111104

__global__ __launch_bounds__(256, 2) void pair_mma(
    const float* __restrict__ H, const float* __restrict__ U, const float* __restrict__ V,
    const float* __restrict__ Wp2, const float* __restrict__ bp2, float* __restrict__ out) {
    extern __shared__ char sm[];
    const uint32_t sb = smem_u32(sm);
    float* w2 = (float*)(sm + OFF_W2);

    const int tid  = threadIdx.x;
    const int lane = tid & 31, wid = tid >> 5;
    const int i_base = blockIdx.x * 8;
    const int j0 = blockIdx.y * 128;

    // ---- stage B (C^T fp16, 34816 B = 2176 uint4) ----
    {
        const uint4* g = (const uint4*)g_bsw;
        uint4* s = (uint4*)(sm + OFF_B);
#pragma unroll
        for (int t = 0; t < 9; ++t) {
            int idx = tid + t * 256;
            if (idx < 2176) s[idx] = g[idx];
        }
    }
    const int j  = tid >> 1;
    const int dh = (tid & 1) << 6;

    // ---- stage HJ: fp16(h_j) tile ----
    {
        const float4* Hj = (const float4*)(H + (size_t)(j0 + j) * HID + dh);
        char* row = sm + OFF_HJ + (uint32_t)j * TSTR + dh * 2;
#pragma unroll
        for (int t = 0; t < 8; ++t) {
            float4 v0 = Hj[2 * t], v1 = Hj[2 * t + 1];
            __half2 a0 = __floats2half2_rn(v0.x, v0.y);
            __half2 a1 = __floats2half2_rn(v0.z, v0.w);
            __half2 a2 = __floats2half2_rn(v1.x, v1.y);
            __half2 a3 = __floats2half2_rn(v1.z, v1.w);
            uint4 o;
            o.x = *(uint32_t*)&a0; o.y = *(uint32_t*)&a1;
            o.z = *(uint32_t*)&a2; o.w = *(uint32_t*)&a3;
            *(uint4*)(row + t * 16) = o;
        }
    }
    // ---- stage his (fp16) and Us (fp32); w2 ----
    if (tid < 128) {
#pragma unroll
        for (int ii = 0; ii < 8; ++ii) {
            float hv = H[(size_t)(i_base + ii) * HID + tid];
            *(__half*)(sm + OFF_HIS + ii * 256 + tid * 2) = __float2half_rn(hv);
            *(float*)(sm + OFF_US + ii * 512 + tid * 4) = U[(size_t)(i_base + ii) * HID + tid];
        }
        w2[tid] = Wp2[tid];
    }
    __syncthreads();

    const uint32_t aAddrBase = sb + OFF_A + (uint32_t)(wid * 16 + (lane & 15)) * TSTR + (lane >> 4) * 16;
    const uint32_t bAddrBase = sb + OFF_B + (uint32_t)(lane & 15) * TSTR + (lane >> 4) * 16;
    const char* hjRow = sm + OFF_HJ + (uint32_t)j * TSTR + dh * 2;
    char* aRow = sm + OFF_A + (uint32_t)j * TSTR + dh * 2;
    const float b2v = bp2[0];
    const int jl0 = wid * 16 + (lane >> 2);    // this thread's first j row (local)
    const int kq  = (lane & 3) * 2;            // k offset within 8-col tile

    for (int ii = 0; ii < 8; ++ii) {
        // ---- build A: A[j][d] = |hj - hi| fp16 ----
        {
            const __half2* hi2 = (const __half2*)(sm + OFF_HIS + ii * 256 + dh * 2);
#pragma unroll
            for (int m = 0; m < 8; ++m) {
                uint4 hv = *(const uint4*)(hjRow + m * 16);
                __half2 j0h = *(__half2*)&hv.x, j1h = *(__half2*)&hv.y;
                __half2 j2h = *(__half2*)&hv.z, j3h = *(__half2*)&hv.w;
                __half2 t0 = __habs2(__hsub2(j0h, hi2[4 * m + 0]));
                __half2 t1 = __habs2(__hsub2(j1h, hi2[4 * m + 1]));
                __half2 t2 = __habs2(__hsub2(j2h, hi2[4 * m + 2]));
                __half2 t3 = __habs2(__hsub2(j3h, hi2[4 * m + 3]));
                uint4 o;
                o.x = *(uint32_t*)&t0; o.y = *(uint32_t*)&t1;
                o.z = *(uint32_t*)&t2; o.w = *(uint32_t*)&t3;
                *(uint4*)(aRow + m * 16) = o;
            }
        }
        __syncthreads();   // A ready

        // ---- MMA: 1 A-fragment x 16 n-tiles per ks, B in two halves ----
        float acc[16][4];
#pragma unroll
        for (int nt = 0; nt < 16; ++nt) {
            acc[nt][0] = 0.f; acc[nt][1] = 0.f; acc[nt][2] = 0.f; acc[nt][3] = 0.f;
        }
#pragma unroll
        for (int ks = 0; ks < 8; ++ks) {
            uint32_t af[4];
            ldm4(af, aAddrBase + ks * 32);
            {
                uint32_t bh[4][4];
#pragma unroll
                for (int p = 0; p < 4; ++p)
                    ldm4(bh[p], bAddrBase + p * (16 * TSTR) + ks * 32);
#pragma unroll
                for (int nt = 0; nt < 8; ++nt)
                    mma_fp16(acc[nt], af, bh[nt >> 1][nt & 1], bh[nt >> 1][(nt & 1) + 2]);
            }
            {
                uint32_t bh[4][4];
#pragma unroll
                for (int p = 0; p < 4; ++p)
                    ldm4(bh[p], bAddrBase + (p + 4) * (16 * TSTR) + ks * 32);
#pragma unroll
                for (int nt = 8; nt < 16; ++nt)
                    mma_fp16(acc[nt], af, bh[(nt - 8) >> 1][nt & 1], bh[(nt - 8) >> 1][(nt & 1) + 2]);
            }
        }

        // ---- epilogue: warp-local relu-dot over full k, quad reduce, direct STG ----
        const float* Usi = (const float*)(sm + OFF_US + ii * 512);
        float p0 = 0.f, p1 = 0.f;
#pragma unroll
        for (int nt = 0; nt < 16; ++nt) {
            const int k = nt * 8 + kq;
            float2 v0 = __ldg((const float2*)(V + (size_t)(j0 + jl0) * HID + k));
            float2 v1 = __ldg((const float2*)(V + (size_t)(j0 + jl0 + 8) * HID + k));
            float u0 = Usi[k], u1 = Usi[k + 1];
            float w0 = w2[k], w1 = w2[k + 1];
            p0 = fmaf(fmaxf(acc[nt][0] + u0 + v0.x, 0.f), w0, p0);
            p0 = fmaf(fmaxf(acc[nt][1] + u1 + v0.y, 0.f), w1, p0);
            p1 = fmaf(fmaxf(acc[nt][2] + u0 + v1.x, 0.f), w0, p1);
            p1 = fmaf(fmaxf(acc[nt][3] + u1 + v1.y, 0.f), w1, p1);
        }
        p0 += __shfl_down_sync(0xffffffffu, p0, 2, 4);
        p0 += __shfl_down_sync(0xffffffffu, p0, 1, 4);
        p1 += __shfl_down_sync(0xffffffffu, p1, 2, 4);
        p1 += __shfl_down_sync(0xffffffffu, p1, 1, 4);
        if ((lane & 3) == 0) {
            out[(size_t)(i_base + ii) * B + j0 + jl0]     = p0 + b2v;
            out[(size_t)(i_base + ii) * B + j0 + jl0 + 8] = p1 + b2v;
        }
        __syncthreads();   // A free for next build
    }
}

// ======================= launch =======================
extern "C" void kernel_launch(void* const* d_in, const int* in_sizes, int n_in,
                              void* d_out, int out_size) {
    const float* x   = (const float*)d_in[0];
    const float* W1  = (const float*)d_in[1];
    const float* b1  = (const float*)d_in[2];
    const float* W2  = (const float*)d_in[3];
    const float* b2  = (const float*)d_in[4];
    const float* Wp1 = (const float*)d_in[5];
    const float* bp1 = (const float*)d_in[6];
    const float* Wp2 = (const float*)d_in[7];
    const float* bp2 = (const float*)d_in[8];
    float* out = (float*)d_out;

    float* sp = nullptr;
    cudaGetSymbolAddress((void**)&sp, g_scratch);
    float* H2 = sp;
    float* U  = sp + B * HID;
    float* V  = sp + 2 * B * HID;

    enc_all<<<288, 512>>>(x, W1, b1, W2, b2, Wp1, bp1, H2, U, V);

    cudaFuncSetAttribute(pair_mma, cudaFuncAttributeMaxDynamicSharedMemorySize, SMEM_PAIR);
    dim3 grid(B / 8, B / 128);
    pair_mma<<<grid, 256, SMEM_PAIR>>>(H2, U, V, Wp2, bp2, out);
}

// round 15
// speedup vs baseline: 1.2595x; 1.0547x over previous
#include <cuda_runtime.h>
#include <cuda_fp16.h>
#include <cstdint>

#define B 512
#define HID 128
#define IN_DIM 595

#define TSTR 272            // tile row stride (bytes) -> conflict-free LDS/ldmatrix
#define TILE_BYTES 34816    // 128 rows * 272

// ---------------- device scratch (no allocations allowed) ----------------
__device__ float g_scratch[3 * B * HID];               // H2, U, V
__device__ __align__(16) unsigned char g_bsw[34816];   // C^T staged fp16

// ======================= helpers =======================
__device__ __forceinline__ uint32_t smem_u32(const void* p) {
    uint32_t a;
    asm("{ .reg .u64 t; cvta.to.shared.u64 t, %1; cvt.u32.u64 %0, t; }" : "=r"(a) : "l"(p));
    return a;
}
__device__ __forceinline__ void ldm4(uint32_t* r, uint32_t addr) {
    asm volatile("ldmatrix.sync.aligned.m8n8.x4.shared.b16 {%0,%1,%2,%3}, [%4];"
                 : "=r"(r[0]), "=r"(r[1]), "=r"(r[2]), "=r"(r[3]) : "r"(addr));
}
__device__ __forceinline__ void mma_fp16(float* c, const uint32_t* a, uint32_t b0, uint32_t b1) {
    asm volatile(
        "mma.sync.aligned.m16n8k16.row.col.f32.f16.f16.f32 "
        "{%0,%1,%2,%3}, {%4,%5,%6,%7}, {%8,%9}, {%0,%1,%2,%3};"
        : "+f"(c[0]), "+f"(c[1]), "+f"(c[2]), "+f"(c[3])
        : "r"(a[0]), "r"(a[1]), "r"(a[2]), "r"(a[3]), "r"(b0), "r"(b1));
}
__device__ __forceinline__ uint32_t habsdiff2(uint32_t a, uint32_t b) {
    __half2 r = __habs2(__hsub2(*(__half2*)&a, *(__half2*)&b));
    return *(uint32_t*)&r;
}
__device__ __forceinline__ uint32_t lds32(uint32_t addr) {
    uint32_t v;
    asm volatile("ld.shared.b32 %0, [%1];" : "=r"(v) : "r"(addr));
    return v;
}

// ======================= fused encoder (whole chain) + prep =======================
__global__ __launch_bounds__(512) void enc_all(const float* __restrict__ x,
                                               const float* __restrict__ W1,
                                               const float* __restrict__ b1,
                                               const float* __restrict__ W2,
                                               const float* __restrict__ b2,
                                               const float* __restrict__ Wp1,
                                               const float* __restrict__ bp1,
                                               float* __restrict__ H2,
                                               float* __restrict__ U, float* __restrict__ V) {
    const int tid = threadIdx.x;
    const int bx = blockIdx.x;
    if (bx >= 256) {
        int idx = (bx - 256) * 512 + tid;           // < 16384
        int k = idx >> 7, d = idx & 127;
        float v = Wp1[(256 + d) * 128 + k];
        *(__half*)(g_bsw + (uint32_t)k * TSTR + d * 2) = __float2half_rn(v);
        return;
    }
    __shared__ float Xs[2 * 608];
    __shared__ float h1s[2][128], h2s[2][128];
    __shared__ float red[3][2][128];
    __shared__ float red2[2][256];
    const int m0 = bx * 2;
    const int n = tid & 127, q = tid >> 7;          // 4-way K split

    for (int idx = tid; idx < 2 * IN_DIM; idx += 512) {
        int r = idx < IN_DIM ? 0 : 1, k = idx < IN_DIM ? idx : idx - IN_DIM;
        Xs[r * 608 + k] = x[(size_t)(m0 + r) * IN_DIM + k];
    }
    __syncthreads();
    {
        const int kb = (IN_DIM * q) >> 2, ke = (IN_DIM * (q + 1)) >> 2;
        float a0 = 0.f, a1 = 0.f;
        const float* Wn = W1 + n;
#pragma unroll 8
        for (int k = kb; k < ke; ++k) {
            float w = __ldg(Wn + k * 128);
            a0 = fmaf(Xs[k], w, a0);
            a1 = fmaf(Xs[608 + k], w, a1);
        }
        if (q) { red[q - 1][0][n] = a0; red[q - 1][1][n] = a1; }
        __syncthreads();
        if (q == 0) {
            float bv = b1[n];
            h1s[0][n] = fmaxf(a0 + red[0][0][n] + red[1][0][n] + red[2][0][n] + bv, 0.f);
            h1s[1][n] = fmaxf(a1 + red[0][1][n] + red[1][1][n] + red[2][1][n] + bv, 0.f);
        }
        __syncthreads();
    }
    {
        float a0 = 0.f, a1 = 0.f;
        const float* Wn = W2 + n;
#pragma unroll 8
        for (int k = q * 32; k < q * 32 + 32; ++k) {
            float w = __ldg(Wn + k * 128);
            a0 = fmaf(h1s[0][k], w, a0);
            a1 = fmaf(h1s[1][k], w, a1);
        }
        if (q) { red[q - 1][0][n] = a0; red[q - 1][1][n] = a1; }
        __syncthreads();
        if (q == 0) {
            float bv = b2[n];
            float r0 = fmaxf(a0 + red[0][0][n] + red[1][0][n] + red[2][0][n] + bv, 0.f);
            float r1 = fmaxf(a1 + red[0][1][n] + red[1][1][n] + red[2][1][n] + bv, 0.f);
            h2s[0][n] = r0; h2s[1][n] = r1;
            H2[(size_t)m0 * 128 + n] = r0;
            H2[(size_t)(m0 + 1) * 128 + n] = r1;
        }
        __syncthreads();
    }
    {
        const int col = tid & 255, q2 = tid >> 8;
        const float* Wc = (col < 128) ? (Wp1 + col) : (Wp1 + 128 * 128 + (col - 128));
        float a0 = 0.f, a1 = 0.f;
#pragma unroll 8
        for (int k = q2 * 64; k < q2 * 64 + 64; ++k) {
            float w = __ldg(Wc + k * 128);
            a0 = fmaf(h2s[0][k], w, a0);
            a1 = fmaf(h2s[1][k], w, a1);
        }
        if (q2) { red2[0][col] = a0; red2[1][col] = a1; }
        __syncthreads();
        if (q2 == 0) {
            float bv = (col < 128) ? bp1[col] : 0.f;
            float r0 = a0 + red2[0][col] + bv;
            float r1 = a1 + red2[1][col] + bv;
            float* dst = (col < 128) ? U : V;
            int c = col & 127;
            dst[(size_t)m0 * 128 + c] = r0;
            dst[(size_t)(m0 + 1) * 128 + c] = r1;
        }
    }
}

// ======================= pairwise kernel: register-built A fragments ================
// grid (64, 4). Warp w owns j rows [w*16, w*16+16), all 128 k.
// A fragment computed in registers from preloaded hj fragment + broadcast hi LDS:
// no STS, no A-ldmatrix, NO barriers in the ii loop.
#define OFF_B   0
#define OFF_HJ  34816
#define OFF_HIS 69632        // 8 * 256 B fp16
#define OFF_US  71680        // 8 * 512 B fp32
#define OFF_W2  75776
#define SMEM_PAIR 76288

__global__ __launch_bounds__(256, 2) void pair_mma(
    const float* __restrict__ H, const float* __restrict__ U, const float* __restrict__ V,
    const float* __restrict__ Wp2, const float* __restrict__ bp2, float* __restrict__ out) {
    extern __shared__ char sm[];
    const uint32_t sb = smem_u32(sm);
    float* w2 = (float*)(sm + OFF_W2);

    const int tid  = threadIdx.x;
    const int lane = tid & 31, wid = tid >> 5;
    const int i_base = blockIdx.x * 8;
    const int j0 = blockIdx.y * 128;

    // ---- stage B (C^T fp16, 34816 B = 2176 uint4) ----
    {
        const uint4* g = (const uint4*)g_bsw;
        uint4* s = (uint4*)(sm + OFF_B);
#pragma unroll
        for (int t = 0; t < 9; ++t) {
            int idx = tid + t * 256;
            if (idx < 2176) s[idx] = g[idx];
        }
    }
    const int j  = tid >> 1;
    const int dh = (tid & 1) << 6;

    // ---- stage HJ: fp16(h_j) tile ----
    {
        const float4* Hj = (const float4*)(H + (size_t)(j0 + j) * HID + dh);
        char* row = sm + OFF_HJ + (uint32_t)j * TSTR + dh * 2;
#pragma unroll
        for (int t = 0; t < 8; ++t) {
            float4 v0 = Hj[2 * t], v1 = Hj[2 * t + 1];
            __half2 a0 = __floats2half2_rn(v0.x, v0.y);
            __half2 a1 = __floats2half2_rn(v0.z, v0.w);
            __half2 a2 = __floats2half2_rn(v1.x, v1.y);
            __half2 a3 = __floats2half2_rn(v1.z, v1.w);
            uint4 o;
            o.x = *(uint32_t*)&a0; o.y = *(uint32_t*)&a1;
            o.z = *(uint32_t*)&a2; o.w = *(uint32_t*)&a3;
            *(uint4*)(row + t * 16) = o;
        }
    }
    // ---- stage his (fp16) and Us (fp32); w2 ----
    if (tid < 128) {
#pragma unroll
        for (int ii = 0; ii < 8; ++ii) {
            float hv = H[(size_t)(i_base + ii) * HID + tid];
            *(__half*)(sm + OFF_HIS + ii * 256 + tid * 2) = __float2half_rn(hv);
            *(float*)(sm + OFF_US + ii * 512 + tid * 4) = U[(size_t)(i_base + ii) * HID + tid];
        }
        w2[tid] = Wp2[tid];
    }
    __syncthreads();   // the ONLY barrier; everything after is read-only smem

    const uint32_t bAddrBase = sb + OFF_B + (uint32_t)(lane & 15) * TSTR + (lane >> 4) * 16;
    const float b2v = bp2[0];
    const int jl0 = wid * 16 + (lane >> 2);    // this thread's first j row (local)
    const int gcb = (lane & 3) * 4;            // byte offset of this thread's k-col pair
    const int kq  = (lane & 3) * 2;

    // ---- preload hj fragments: hjf[ks] = {r0-klo, r0+8-klo, r0-khi, r0+8-khi} ----
    uint32_t hjf[8][4];
    {
        const uint32_t rowA = sb + OFF_HJ + (uint32_t)jl0 * TSTR + gcb;
        const uint32_t rowB = rowA + 8 * TSTR;
#pragma unroll
        for (int ks = 0; ks < 8; ++ks) {
            hjf[ks][0] = lds32(rowA + ks * 32);
            hjf[ks][1] = lds32(rowB + ks * 32);
            hjf[ks][2] = lds32(rowA + ks * 32 + 16);
            hjf[ks][3] = lds32(rowB + ks * 32 + 16);
        }
    }

    for (int ii = 0; ii < 8; ++ii) {
        const uint32_t hisBase = sb + OFF_HIS + ii * 256 + gcb;

        float acc[16][4];
#pragma unroll
        for (int nt = 0; nt < 16; ++nt) {
            acc[nt][0] = 0.f; acc[nt][1] = 0.f; acc[nt][2] = 0.f; acc[nt][3] = 0.f;
        }
#pragma unroll
        for (int ks = 0; ks < 8; ++ks) {
            uint32_t hlo = lds32(hisBase + ks * 32);
            uint32_t hhi = lds32(hisBase + ks * 32 + 16);
            uint32_t af[4];
            af[0] = habsdiff2(hjf[ks][0], hlo);
            af[1] = habsdiff2(hjf[ks][1], hlo);
            af[2] = habsdiff2(hjf[ks][2], hhi);
            af[3] = habsdiff2(hjf[ks][3], hhi);
            {
                uint32_t bh[4][4];
#pragma unroll
                for (int p = 0; p < 4; ++p)
                    ldm4(bh[p], bAddrBase + p * (16 * TSTR) + ks * 32);
#pragma unroll
                for (int nt = 0; nt < 8; ++nt)
                    mma_fp16(acc[nt], af, bh[nt >> 1][nt & 1], bh[nt >> 1][(nt & 1) + 2]);
            }
            {
                uint32_t bh[4][4];
#pragma unroll
                for (int p = 0; p < 4; ++p)
                    ldm4(bh[p], bAddrBase + (p + 4) * (16 * TSTR) + ks * 32);
#pragma unroll
                for (int nt = 8; nt < 16; ++nt)
                    mma_fp16(acc[nt], af, bh[(nt - 8) >> 1][nt & 1], bh[(nt - 8) >> 1][(nt & 1) + 2]);
            }
        }

        // ---- epilogue (round-12 C-fragment mapping): c0,c1 -> row jl0; c2,c3 -> jl0+8 ----
        const float* Usi = (const float*)(sm + OFF_US + ii * 512);
        float p0 = 0.f, p1 = 0.f;
#pragma unroll
        for (int nt = 0; nt < 16; ++nt) {
            const int k = nt * 8 + kq;
            float2 v0 = __ldg((const float2*)(V + (size_t)(j0 + jl0) * HID + k));
            float2 v1 = __ldg((const float2*)(V + (size_t)(j0 + jl0 + 8) * HID + k));
            float u0 = Usi[k], u1 = Usi[k + 1];
            float w0 = w2[k], w1 = w2[k + 1];
            p0 = fmaf(fmaxf(acc[nt][0] + u0 + v0.x, 0.f), w0, p0);
            p0 = fmaf(fmaxf(acc[nt][1] + u1 + v0.y, 0.f), w1, p0);
            p1 = fmaf(fmaxf(acc[nt][2] + u0 + v1.x, 0.f), w0, p1);
            p1 = fmaf(fmaxf(acc[nt][3] + u1 + v1.y, 0.f), w1, p1);
        }
        p0 += __shfl_down_sync(0xffffffffu, p0, 2, 4);
        p0 += __shfl_down_sync(0xffffffffu, p0, 1, 4);
        p1 += __shfl_down_sync(0xffffffffu, p1, 2, 4);
        p1 += __shfl_down_sync(0xffffffffu, p1, 1, 4);
        if ((lane & 3) == 0) {
            out[(size_t)(i_base + ii) * B + j0 + jl0]     = p0 + b2v;
            out[(size_t)(i_base + ii) * B + j0 + jl0 + 8] = p1 + b2v;
        }
    }
}

// ======================= launch =======================
extern "C" void kernel_launch(void* const* d_in, const int* in_sizes, int n_in,
                              void* d_out, int out_size) {
    const float* x   = (const float*)d_in[0];
    const float* W1  = (const float*)d_in[1];
    const float* b1  = (const float*)d_in[2];
    const float* W2  = (const float*)d_in[3];
    const float* b2  = (const float*)d_in[4];
    const float* Wp1 = (const float*)d_in[5];
    const float* bp1 = (const float*)d_in[6];
    const float* Wp2 = (const float*)d_in[7];
    const float* bp2 = (const float*)d_in[8];
    float* out = (float*)d_out;

    float* sp = nullptr;
    cudaGetSymbolAddress((void**)&sp, g_scratch);
    float* H2 = sp;
    float* U  = sp + B * HID;
    float* V  = sp + 2 * B * HID;

    enc_all<<<288, 512>>>(x, W1, b1, W2, b2, Wp1, bp1, H2, U, V);

    cudaFuncSetAttribute(pair_mma, cudaFuncAttributeMaxDynamicSharedMemorySize, SMEM_PAIR);
    dim3 grid(B / 8, B / 128);
    pair_mma<<<grid, 256, SMEM_PAIR>>>(H2, U, V, Wp2, bp2, out);
}

// round 16
// speedup vs baseline: 1.4620x; 1.1607x over previous
#include <cuda_runtime.h>
#include <cuda_fp16.h>
#include <cstdint>

#define B 512
#define HID 128
#define IN_DIM 595

#define TSTR 272            // B tile row stride (bytes) -> conflict-free ldmatrix
#define HJSTR 288           // permuted HJ row stride (8-bank offset/row -> conflict-free lds64)

// ---------------- device scratch (no allocations allowed) ----------------
__device__ float g_scratch[3 * B * HID];               // H2, U, V
__device__ __align__(16) unsigned char g_bsw[34816];   // C^T staged fp16

// ======================= helpers =======================
__device__ __forceinline__ uint32_t smem_u32(const void* p) {
    uint32_t a;
    asm("{ .reg .u64 t; cvta.to.shared.u64 t, %1; cvt.u32.u64 %0, t; }" : "=r"(a) : "l"(p));
    return a;
}
__device__ __forceinline__ void ldm4(uint32_t* r, uint32_t addr) {
    asm volatile("ldmatrix.sync.aligned.m8n8.x4.shared.b16 {%0,%1,%2,%3}, [%4];"
                 : "=r"(r[0]), "=r"(r[1]), "=r"(r[2]), "=r"(r[3]) : "r"(addr));
}
__device__ __forceinline__ void mma_fp16(float* c, const uint32_t* a, uint32_t b0, uint32_t b1) {
    asm volatile(
        "mma.sync.aligned.m16n8k16.row.col.f32.f16.f16.f32 "
        "{%0,%1,%2,%3}, {%4,%5,%6,%7}, {%8,%9}, {%0,%1,%2,%3};"
        : "+f"(c[0]), "+f"(c[1]), "+f"(c[2]), "+f"(c[3])
        : "r"(a[0]), "r"(a[1]), "r"(a[2]), "r"(a[3]), "r"(b0), "r"(b1));
}
__device__ __forceinline__ uint32_t habsdiff2(uint32_t a, uint32_t b) {
    __half2 r = __habs2(__hsub2(*(__half2*)&a, *(__half2*)&b));
    return *(uint32_t*)&r;
}
__device__ __forceinline__ uint2 lds64(uint32_t addr) {
    uint2 v;
    asm volatile("ld.shared.v2.b32 {%0,%1}, [%2];" : "=r"(v.x), "=r"(v.y) : "r"(addr));
    return v;
}

// ======================= fused encoder (whole chain) + prep =======================
__global__ __launch_bounds__(512) void enc_all(const float* __restrict__ x,
                                               const float* __restrict__ W1,
                                               const float* __restrict__ b1,
                                               const float* __restrict__ W2,
                                               const float* __restrict__ b2,
                                               const float* __restrict__ Wp1,
                                               const float* __restrict__ bp1,
                                               float* __restrict__ H2,
                                               float* __restrict__ U, float* __restrict__ V) {
    const int tid = threadIdx.x;
    const int bx = blockIdx.x;
    if (bx >= 256) {
        int idx = (bx - 256) * 512 + tid;           // < 16384
        int k = idx >> 7, d = idx & 127;
        float v = Wp1[(256 + d) * 128 + k];
        *(__half*)(g_bsw + (uint32_t)k * TSTR + d * 2) = __float2half_rn(v);
        return;
    }
    __shared__ float Xs[2 * 608];
    __shared__ float h1s[2][128], h2s[2][128];
    __shared__ float red[3][2][128];
    __shared__ float red2[2][256];
    const int m0 = bx * 2;
    const int n = tid & 127, q = tid >> 7;          // 4-way K split

    for (int idx = tid; idx < 2 * IN_DIM; idx += 512) {
        int r = idx < IN_DIM ? 0 : 1, k = idx < IN_DIM ? idx : idx - IN_DIM;
        Xs[r * 608 + k] = x[(size_t)(m0 + r) * IN_DIM + k];
    }
    __syncthreads();
    {
        const int kb = (IN_DIM * q) >> 2, ke = (IN_DIM * (q + 1)) >> 2;
        float a0 = 0.f, a1 = 0.f;
        const float* Wn = W1 + n;
#pragma unroll 8
        for (int k = kb; k < ke; ++k) {
            float w = __ldg(Wn + k * 128);
            a0 = fmaf(Xs[k], w, a0);
            a1 = fmaf(Xs[608 + k], w, a1);
        }
        if (q) { red[q - 1][0][n] = a0; red[q - 1][1][n] = a1; }
        __syncthreads();
        if (q == 0) {
            float bv = b1[n];
            h1s[0][n] = fmaxf(a0 + red[0][0][n] + red[1][0][n] + red[2][0][n] + bv, 0.f);
            h1s[1][n] = fmaxf(a1 + red[0][1][n] + red[1][1][n] + red[2][1][n] + bv, 0.f);
        }
        __syncthreads();
    }
    {
        float a0 = 0.f, a1 = 0.f;
        const float* Wn = W2 + n;
#pragma unroll 8
        for (int k = q * 32; k < q * 32 + 32; ++k) {
            float w = __ldg(Wn + k * 128);
            a0 = fmaf(h1s[0][k], w, a0);
            a1 = fmaf(h1s[1][k], w, a1);
        }
        if (q) { red[q - 1][0][n] = a0; red[q - 1][1][n] = a1; }
        __syncthreads();
        if (q == 0) {
            float bv = b2[n];
            float r0 = fmaxf(a0 + red[0][0][n] + red[1][0][n] + red[2][0][n] + bv, 0.f);
            float r1 = fmaxf(a1 + red[0][1][n] + red[1][1][n] + red[2][1][n] + bv, 0.f);
            h2s[0][n] = r0; h2s[1][n] = r1;
            H2[(size_t)m0 * 128 + n] = r0;
            H2[(size_t)(m0 + 1) * 128 + n] = r1;
        }
        __syncthreads();
    }
    {
        const int col = tid & 255, q2 = tid >> 8;
        const float* Wc = (col < 128) ? (Wp1 + col) : (Wp1 + 128 * 128 + (col - 128));
        float a0 = 0.f, a1 = 0.f;
#pragma unroll 8
        for (int k = q2 * 64; k < q2 * 64 + 64; ++k) {
            float w = __ldg(Wc + k * 128);
            a0 = fmaf(h2s[0][k], w, a0);
            a1 = fmaf(h2s[1][k], w, a1);
        }
        if (q2) { red2[0][col] = a0; red2[1][col] = a1; }
        __syncthreads();
        if (q2 == 0) {
            float bv = (col < 128) ? bp1[col] : 0.f;
            float r0 = a0 + red2[0][col] + bv;
            float r1 = a1 + red2[1][col] + bv;
            float* dst = (col < 128) ? U : V;
            int c = col & 127;
            dst[(size_t)m0 * 128 + c] = r0;
            dst[(size_t)(m0 + 1) * 128 + c] = r1;
        }
    }
}

// ======================= pairwise kernel: 32j x 64k warps, permuted HJ/HIS ==========
// grid (64, 4). 8 warps = 4 j-groups (32 rows) x 2 k-halves (64 cols).
// HJ/HIS stored quad-permuted: {klo,khi} adjacent -> 1 lds64 per (row,ks).
// 2-way k reduction via double-buffered red, ONE sync per ii.
#define OFF_B    0
#define OFF_HJP  34816       // 128 rows * 288 = 36864
#define OFF_HIS  71680       // 8 ii * 256 B
#define OFF_US   73728       // 8 * 512 B fp32
#define OFF_W2   77824       // 512
#define OFF_RED  78336       // 2 buf * 2 khalf * 128 * 4 = 4096
#define SMEM_PAIR 82432

__global__ __launch_bounds__(256, 2) void pair_mma(
    const float* __restrict__ H, const float* __restrict__ U, const float* __restrict__ V,
    const float* __restrict__ Wp2, const float* __restrict__ bp2, float* __restrict__ out) {
    extern __shared__ char sm[];
    const uint32_t sb = smem_u32(sm);
    float* w2  = (float*)(sm + OFF_W2);
    float* red = (float*)(sm + OFF_RED);   // [buf][khalf][128]

    const int tid  = threadIdx.x;
    const int lane = tid & 31, wid = tid >> 5;
    const int jg = wid & 3, khalf = wid >> 2;
    const int i_base = blockIdx.x * 8;
    const int j0 = blockIdx.y * 128;

    // ---- stage B (C^T fp16, 34816 B = 2176 uint4) ----
    {
        const uint4* g = (const uint4*)g_bsw;
        uint4* s = (uint4*)(sm + OFF_B);
#pragma unroll
        for (int t = 0; t < 9; ++t) {
            int idx = tid + t * 256;
            if (idx < 2176) s[idx] = g[idx];
        }
    }
    const int j  = tid >> 1;
    const int dhalf = tid & 1;             // ks groups [dhalf*4, dhalf*4+4)

    // ---- stage HJP: quad-permuted fp16(h_j): [row][ks][qd] = {klo2, khi2} ----
    {
        const float4* Hj = (const float4*)(H + (size_t)(j0 + j) * HID + dhalf * 64);
        char* rowp = sm + OFF_HJP + (uint32_t)j * HJSTR;
#pragma unroll
        for (int g = 0; g < 4; ++g) {                 // ks = dhalf*4 + g, d base = ks*16
            const int ks = dhalf * 4 + g;
            float4 vlo = Hj[g * 4 + 0];               // d +0..3
            float4 vlo2 = Hj[g * 4 + 1];              // d +4..7
            float4 vhi = Hj[g * 4 + 2];               // d +8..11
            float4 vhi2 = Hj[g * 4 + 3];              // d +12..15
            __half2 l0 = __floats2half2_rn(vlo.x, vlo.y);
            __half2 l1 = __floats2half2_rn(vlo.z, vlo.w);
            __half2 l2 = __floats2half2_rn(vlo2.x, vlo2.y);
            __half2 l3 = __floats2half2_rn(vlo2.z, vlo2.w);
            __half2 h0 = __floats2half2_rn(vhi.x, vhi.y);
            __half2 h1 = __floats2half2_rn(vhi.z, vhi.w);
            __half2 h2 = __floats2half2_rn(vhi2.x, vhi2.y);
            __half2 h3 = __floats2half2_rn(vhi2.z, vhi2.w);
            uint32_t* w = (uint32_t*)(rowp + ks * 32);
            w[0] = *(uint32_t*)&l0; w[1] = *(uint32_t*)&h0;   // qd 0
            w[2] = *(uint32_t*)&l1; w[3] = *(uint32_t*)&h1;   // qd 1
            w[4] = *(uint32_t*)&l2; w[5] = *(uint32_t*)&h2;   // qd 2
            w[6] = *(uint32_t*)&l3; w[7] = *(uint32_t*)&h3;   // qd 3
        }
    }
    // ---- stage HIS (quad-permuted) and Us; w2 ----
    if (tid < 128) {
        const int d = tid;
        const int ks = d >> 4, rem = d & 15;
        const int qd = (rem & 7) >> 1, half = rem >> 3, byt = rem & 1;
        const uint32_t off = ks * 32 + qd * 8 + half * 4 + byt * 2;
#pragma unroll
        for (int ii = 0; ii < 8; ++ii) {
            float hv = H[(size_t)(i_base + ii) * HID + d];
            *(__half*)(sm + OFF_HIS + ii * 256 + off) = __float2half_rn(hv);
            *(float*)(sm + OFF_US + ii * 512 + d * 4) = U[(size_t)(i_base + ii) * HID + d];
        }
        w2[tid] = Wp2[tid];
    }
    __syncthreads();

    const uint32_t bAddrBase = sb + OFF_B + (uint32_t)(khalf * 64 + (lane & 15)) * TSTR + (lane >> 4) * 16;
    const float b2v = bp2[0];
    const int rq  = lane >> 2;             // 0..7
    const int qd  = lane & 3;
    const int r0l = jg * 32 + rq;          // local row of mt0-c0 (rows r0l, +8, +16, +24)
    const int kq  = qd * 2;
    const uint32_t hj0 = sb + OFF_HJP + (uint32_t)r0l * HJSTR + qd * 8;
    const uint32_t hj1 = hj0 + 8 * HJSTR;
    const uint32_t hj2 = hj0 + 16 * HJSTR;
    const uint32_t hj3 = hj0 + 24 * HJSTR;

    for (int ii = 0; ii < 8; ++ii) {
        const uint32_t hisB = sb + OFF_HIS + ii * 256 + qd * 8;

        float acc[2][8][4];
#pragma unroll
        for (int mt = 0; mt < 2; ++mt)
#pragma unroll
            for (int nt = 0; nt < 8; ++nt) {
                acc[mt][nt][0] = 0.f; acc[mt][nt][1] = 0.f;
                acc[mt][nt][2] = 0.f; acc[mt][nt][3] = 0.f;
            }
#pragma unroll
        for (int ks = 0; ks < 8; ++ks) {
            uint2 hi = lds64(hisB + ks * 32);
            uint2 a0 = lds64(hj0 + ks * 32);
            uint2 a1 = lds64(hj1 + ks * 32);
            uint2 a2 = lds64(hj2 + ks * 32);
            uint2 a3 = lds64(hj3 + ks * 32);
            uint32_t af0[4], af1[4];
            af0[0] = habsdiff2(a0.x, hi.x); af0[1] = habsdiff2(a1.x, hi.x);
            af0[2] = habsdiff2(a0.y, hi.y); af0[3] = habsdiff2(a1.y, hi.y);
            af1[0] = habsdiff2(a2.x, hi.x); af1[1] = habsdiff2(a3.x, hi.x);
            af1[2] = habsdiff2(a2.y, hi.y); af1[3] = habsdiff2(a3.y, hi.y);
            uint32_t bh[4][4];
#pragma unroll
            for (int p = 0; p < 4; ++p)
                ldm4(bh[p], bAddrBase + p * (16 * TSTR) + ks * 32);
#pragma unroll
            for (int nt = 0; nt < 8; ++nt) {
                uint32_t b0 = bh[nt >> 1][nt & 1], b1 = bh[nt >> 1][(nt & 1) + 2];
                mma_fp16(acc[0][nt], af0, b0, b1);
                mma_fp16(acc[1][nt], af1, b0, b1);
            }
        }

        // ---- epilogue: relu(acc + U + V).w2 over this warp's 64 k, quad reduce ----
        const float* Usi = (const float*)(sm + OFF_US + ii * 512);
        float p0 = 0.f, p1 = 0.f, p2 = 0.f, p3 = 0.f;
#pragma unroll
        for (int nt = 0; nt < 8; ++nt) {
            const int k = khalf * 64 + nt * 8 + kq;
            float2 v0 = __ldg((const float2*)(V + (size_t)(j0 + r0l) * HID + k));
            float2 v1 = __ldg((const float2*)(V + (size_t)(j0 + r0l + 8) * HID + k));
            float2 v2 = __ldg((const float2*)(V + (size_t)(j0 + r0l + 16) * HID + k));
            float2 v3 = __ldg((const float2*)(V + (size_t)(j0 + r0l + 24) * HID + k));
            float u0 = Usi[k], u1 = Usi[k + 1];
            float w0 = w2[k], w1 = w2[k + 1];
            p0 = fmaf(fmaxf(acc[0][nt][0] + u0 + v0.x, 0.f), w0, p0);
            p0 = fmaf(fmaxf(acc[0][nt][1] + u1 + v0.y, 0.f), w1, p0);
            p1 = fmaf(fmaxf(acc[0][nt][2] + u0 + v1.x, 0.f), w0, p1);
            p1 = fmaf(fmaxf(acc[0][nt][3] + u1 + v1.y, 0.f), w1, p1);
            p2 = fmaf(fmaxf(acc[1][nt][0] + u0 + v2.x, 0.f), w0, p2);
            p2 = fmaf(fmaxf(acc[1][nt][1] + u1 + v2.y, 0.f), w1, p2);
            p3 = fmaf(fmaxf(acc[1][nt][2] + u0 + v3.x, 0.f), w0, p3);
            p3 = fmaf(fmaxf(acc[1][nt][3] + u1 + v3.y, 0.f), w1, p3);
        }
        p0 += __shfl_down_sync(0xffffffffu, p0, 2, 4);
        p0 += __shfl_down_sync(0xffffffffu, p0, 1, 4);
        p1 += __shfl_down_sync(0xffffffffu, p1, 2, 4);
        p1 += __shfl_down_sync(0xffffffffu, p1, 1, 4);
        p2 += __shfl_down_sync(0xffffffffu, p2, 2, 4);
        p2 += __shfl_down_sync(0xffffffffu, p2, 1, 4);
        p3 += __shfl_down_sync(0xffffffffu, p3, 2, 4);
        p3 += __shfl_down_sync(0xffffffffu, p3, 1, 4);
        float* rb = red + (ii & 1) * 256 + khalf * 128;
        if (qd == 0) {
            rb[r0l]      = p0;
            rb[r0l + 8]  = p1;
            rb[r0l + 16] = p2;
            rb[r0l + 24] = p3;
        }
        __syncthreads();
        if (tid < 128) {
            const float* r0 = red + (ii & 1) * 256;
            out[(size_t)(i_base + ii) * B + j0 + tid] = r0[tid] + r0[128 + tid] + b2v;
        }
    }
}

// ======================= launch =======================
extern "C" void kernel_launch(void* const* d_in, const int* in_sizes, int n_in,
                              void* d_out, int out_size) {
    const float* x   = (const float*)d_in[0];
    const float* W1  = (const float*)d_in[1];
    const float* b1  = (const float*)d_in[2];
    const float* W2  = (const float*)d_in[3];
    const float* b2  = (const float*)d_in[4];
    const float* Wp1 = (const float*)d_in[5];
    const float* bp1 = (const float*)d_in[6];
    const float* Wp2 = (const float*)d_in[7];
    const float* bp2 = (const float*)d_in[8];
    float* out = (float*)d_out;

    float* sp = nullptr;
    cudaGetSymbolAddress((void**)&sp, g_scratch);
    float* H2 = sp;
    float* U  = sp + B * HID;
    float* V  = sp + 2 * B * HID;

    enc_all<<<288, 512>>>(x, W1, b1, W2, b2, Wp1, bp1, H2, U, V);

    cudaFuncSetAttribute(pair_mma, cudaFuncAttributeMaxDynamicSharedMemorySize, SMEM_PAIR);
    dim3 grid(B / 8, B / 128);
    pair_mma<<<grid, 256, SMEM_PAIR>>>(H2, U, V, Wp2, bp2, out);
}